// round 5
// baseline (speedup 1.0000x reference)
#include <cuda_runtime.h>
#include <cuda_bf16.h>
#include <math.h>
#include <stdint.h>

// Problem dims (fixed)
#define BB 2
#define SS 2048
#define DD 1024
#define HH 16
#define DHH 64
#define FF 4096
#define NTOK (BB*SS)   // 4096

// ---------------- scratch (device globals) -----------------------------------
__device__ __nv_bfloat16 g_h_hi [NTOK*DD], g_h_lo [NTOK*DD];
__device__ __nv_bfloat16 g_q_hi [NTOK*DD], g_q_lo [NTOK*DD];
__device__ __nv_bfloat16 g_k_hi [NTOK*DD], g_k_lo [NTOK*DD];
__device__ __nv_bfloat16 g_v_hi [NTOK*DD], g_v_lo [NTOK*DD];
__device__ __nv_bfloat16 g_o_hi [NTOK*DD], g_o_lo [NTOK*DD];
__device__ float         g_add1[NTOK*DD];
__device__ __nv_bfloat16 g_h2_hi[NTOK*DD], g_h2_lo[NTOK*DD];
__device__ __nv_bfloat16 g_act_hi[NTOK*FF], g_act_lo[NTOK*FF];
__device__ __nv_bfloat16 g_wqkv_hi[3*DD*DD], g_wqkv_lo[3*DD*DD];
__device__ __nv_bfloat16 g_wo_hi[DD*DD], g_wo_lo[DD*DD];
__device__ __nv_bfloat16 g_w1_hi[DD*FF], g_w1_lo[DD*FF];
__device__ __nv_bfloat16 g_w2_hi[FF*DD], g_w2_lo[FF*DD];

// ---------------- helpers ------------------------------------------------------
__device__ __forceinline__ uint32_t smem_u32(const void* p) {
    uint32_t a;
    asm("{ .reg .u64 t; cvta.to.shared.u64 t, %1; cvt.u32.u64 %0, t; }" : "=r"(a) : "l"(p));
    return a;
}

__device__ __forceinline__ void cp_async16(uint32_t dst, const void* src) {
    asm volatile("cp.async.cg.shared.global [%0], [%1], 16;"
                 :: "r"(dst), "l"(src) : "memory");
}
__device__ __forceinline__ void cp_commit() {
    asm volatile("cp.async.commit_group;" ::: "memory");
}
template<int N>
__device__ __forceinline__ void cp_wait() {
    asm volatile("cp.async.wait_group %0;" :: "n"(N) : "memory");
}

__device__ __forceinline__ void ldsm_x4(uint32_t* r, uint32_t addr) {
    asm volatile("ldmatrix.sync.aligned.m8n8.x4.shared.b16 {%0,%1,%2,%3}, [%4];"
                 : "=r"(r[0]), "=r"(r[1]), "=r"(r[2]), "=r"(r[3]) : "r"(addr));
}
__device__ __forceinline__ void ldsm_x4_t(uint32_t* r, uint32_t addr) {
    asm volatile("ldmatrix.sync.aligned.m8n8.x4.trans.shared.b16 {%0,%1,%2,%3}, [%4];"
                 : "=r"(r[0]), "=r"(r[1]), "=r"(r[2]), "=r"(r[3]) : "r"(addr));
}

__device__ __forceinline__ void mma16816(float* d, const uint32_t* a, const uint32_t* b) {
    asm volatile(
        "mma.sync.aligned.m16n8k16.row.col.f32.bf16.bf16.f32 "
        "{%0,%1,%2,%3}, {%4,%5,%6,%7}, {%8,%9}, {%0,%1,%2,%3};"
        : "+f"(d[0]), "+f"(d[1]), "+f"(d[2]), "+f"(d[3])
        : "r"(a[0]), "r"(a[1]), "r"(a[2]), "r"(a[3]), "r"(b[0]), "r"(b[1]));
}

__device__ __forceinline__ uint32_t packbf(float a, float b) {
    __nv_bfloat162 t = __floats2bfloat162_rn(a, b);
    return *reinterpret_cast<uint32_t*>(&t);
}
__device__ __forceinline__ float bfres(float a) {
    __nv_bfloat16 h = __float2bfloat16(a);
    return a - __bfloat162float(h);
}

// ---------------- LayerNorm -> bf16 hi/lo split --------------------------------
__global__ void ln_split_kernel(const float* __restrict__ x,
                                const float* __restrict__ g,
                                const float* __restrict__ b,
                                __nv_bfloat16* __restrict__ yhi,
                                __nv_bfloat16* __restrict__ ylo) {
    const int row = blockIdx.x;
    const int tid = threadIdx.x;   // 256
    const float* xr = x + (size_t)row * DD;

    float v[4];
    float s = 0.f, s2 = 0.f;
#pragma unroll
    for (int i = 0; i < 4; ++i) {
        v[i] = xr[tid + i * 256];
        s += v[i]; s2 += v[i] * v[i];
    }
    for (int off = 16; off > 0; off >>= 1) {
        s  += __shfl_down_sync(0xffffffffu, s,  off);
        s2 += __shfl_down_sync(0xffffffffu, s2, off);
    }
    __shared__ float rs[8], rs2[8];
    if ((tid & 31) == 0) { rs[tid >> 5] = s; rs2[tid >> 5] = s2; }
    __syncthreads();
    if (tid < 8) { s = rs[tid]; s2 = rs2[tid]; } else { s = 0.f; s2 = 0.f; }
    if (tid < 32) {
        for (int off = 4; off > 0; off >>= 1) {
            s  += __shfl_down_sync(0xffffffffu, s,  off);
            s2 += __shfl_down_sync(0xffffffffu, s2, off);
        }
        if (tid == 0) { rs[0] = s; rs2[0] = s2; }
    }
    __syncthreads();
    const float mean = rs[0] * (1.0f / DD);
    const float var  = rs2[0] * (1.0f / DD) - mean * mean;
    const float inv  = rsqrtf(var + 1e-5f);
    __nv_bfloat16* yh = yhi + (size_t)row * DD;
    __nv_bfloat16* yl = ylo + (size_t)row * DD;
#pragma unroll
    for (int i = 0; i < 4; ++i) {
        const int c = tid + i * 256;
        float o = (v[i] - mean) * inv * g[c] + b[c];
        __nv_bfloat16 h = __float2bfloat16(o);
        yh[c] = h;
        yl[c] = __float2bfloat16(o - __bfloat162float(h));
    }
}

// ---------------- weight transpose + split: w[K,N] fp32 -> [N,K] bf16 hi/lo ----
__global__ void wsplit_kernel(const float* __restrict__ w,
                              __nv_bfloat16* __restrict__ bhi,
                              __nv_bfloat16* __restrict__ blo, int K, int N) {
    __shared__ float t[32][33];
    const int bx = blockIdx.x;   // n tile
    const int by = blockIdx.y;   // k tile
    const int tx = threadIdx.x & 31;
    const int ty = threadIdx.x >> 5;   // 0..7
#pragma unroll
    for (int i = 0; i < 32; i += 8)
        t[ty + i][tx] = w[(size_t)(by * 32 + ty + i) * N + bx * 32 + tx];
    __syncthreads();
#pragma unroll
    for (int i = 0; i < 32; i += 8) {
        const int n = bx * 32 + ty + i;
        const int k = by * 32 + tx;
        float v = t[tx][ty + i];
        __nv_bfloat16 h = __float2bfloat16(v);
        bhi[(size_t)n * K + k] = h;
        blo[(size_t)n * K + k] = __float2bfloat16(v - __bfloat162float(h));
    }
}

// ---------------- mma.sync GEMM: C[M,N] = A[M,K] @ B^T ([N,K] stored) ---------
// bf16x3: C = Ahi*Bhi + Alo*Bhi + Ahi*Blo, fp32 accumulate.
// SPLIT3: output columns [0,3072) routed to 3 separate [M,1024] dst buffers.
#define ROWB 80
#define TILESZ (128*ROWB)
#define BUFSZ  (4*TILESZ)
#define GEMM_SMEM (2*BUFSZ + 512)

__device__ __forceinline__ void issue_chunk(const __nv_bfloat16* const* tp, int k0,
                                            uint32_t buf, int tid, int K) {
#pragma unroll
    for (int t = 0; t < 4; ++t) {
#pragma unroll
        for (int u = 0; u < 2; ++u) {
            const int lin = tid + u * 256;
            const int r = lin >> 2;
            const int c4 = lin & 3;
            const void* src = tp[t] + (size_t)r * K + k0 + c4 * 8;
            cp_async16(buf + t * TILESZ + r * ROWB + c4 * 16, src);
        }
    }
    cp_commit();
}

template<int OUTMODE /*0=f32, 1=bf16 pair*/, bool HAS_RES, bool DO_GELU, bool SPLIT3>
__global__ void __launch_bounds__(256)
tc_gemm(const __nv_bfloat16* __restrict__ Ahi, const __nv_bfloat16* __restrict__ Alo,
        const __nv_bfloat16* __restrict__ Bhi, const __nv_bfloat16* __restrict__ Blo,
        const float* __restrict__ bias, const float* __restrict__ bias1,
        const float* __restrict__ bias2,
        const float* __restrict__ res,
        float* __restrict__ Cf,
        __nv_bfloat16* __restrict__ Chi,  __nv_bfloat16* __restrict__ Clo,
        __nv_bfloat16* __restrict__ Chi1, __nv_bfloat16* __restrict__ Clo1,
        __nv_bfloat16* __restrict__ Chi2, __nv_bfloat16* __restrict__ Clo2,
        int M, int N, int K) {
    extern __shared__ char smem[];
    const uint32_t sbase = smem_u32(smem);
    float* bias_s = (float*)(smem + 2 * BUFSZ);

    const int tid  = threadIdx.x;
    const int wid  = tid >> 5;
    const int lane = tid & 31;
    const int wm = wid >> 1;
    const int wn = wid & 1;
    const int bx = blockIdx.x, by = blockIdx.y;

    // output routing
    const float* bp = bias;
    __nv_bfloat16* chp = Chi;
    __nv_bfloat16* clp = Clo;
    int nout = N;
    int ncol0 = bx * 128;
    if (SPLIT3) {
        const int seg = bx >> 3;
        bp  = (seg == 0) ? bias : (seg == 1) ? bias1 : bias2;
        chp = (seg == 0) ? Chi  : (seg == 1) ? Chi1  : Chi2;
        clp = (seg == 0) ? Clo  : (seg == 1) ? Clo1  : Clo2;
        nout = DD;
        ncol0 = (bx & 7) * 128;
    }
    if (tid < 128) bias_s[tid] = bp[ncol0 + tid];

    const size_t aoff = (size_t)by * 128 * K;
    const size_t boff = (size_t)bx * 128 * K;
    const __nv_bfloat16* tp[4] = { Ahi + aoff, Alo + aoff, Bhi + boff, Blo + boff };

    const int nchunk = K >> 5;

    float acc[2][8][4];
#pragma unroll
    for (int mt = 0; mt < 2; ++mt)
#pragma unroll
        for (int nt = 0; nt < 8; ++nt)
#pragma unroll
            for (int e = 0; e < 4; ++e) acc[mt][nt][e] = 0.f;

    const int a_row = wm * 32 + (lane & 15);
    const int a_kof = (lane >> 4) << 3;
    const int b_row = wn * 64 + (lane & 7) + ((lane >> 4) << 3);
    const int b_kof = ((lane >> 3) & 1) << 3;

    issue_chunk(tp, 0, sbase, tid, K);

    for (int i = 0; i < nchunk; ++i) {
        if (i + 1 < nchunk)
            issue_chunk(tp, (i + 1) << 5, sbase + ((i + 1) & 1) * BUFSZ, tid, K);
        if (i + 1 < nchunk) cp_wait<1>(); else cp_wait<0>();
        __syncthreads();

        const uint32_t buf = sbase + (i & 1) * BUFSZ;
        const uint32_t aAh = buf + a_row * ROWB;
        const uint32_t aAl = aAh + TILESZ;
        const uint32_t aBh = buf + 2 * TILESZ + b_row * ROWB;
        const uint32_t aBl = aBh + TILESZ;

#pragma unroll
        for (int ks = 0; ks < 2; ++ks) {
            const int ak = (ks * 16 + a_kof) * 2;
            const int bk = (ks * 16 + b_kof) * 2;
            uint32_t ah[2][4], al[2][4], bh[8][2], bl[8][2];
#pragma unroll
            for (int mt = 0; mt < 2; ++mt) {
                ldsm_x4(ah[mt], aAh + mt * 16 * ROWB + ak);
                ldsm_x4(al[mt], aAl + mt * 16 * ROWB + ak);
            }
#pragma unroll
            for (int p = 0; p < 4; ++p) {
                uint32_t r[4];
                ldsm_x4(r, aBh + p * 16 * ROWB + bk);
                bh[2*p][0] = r[0]; bh[2*p][1] = r[1];
                bh[2*p+1][0] = r[2]; bh[2*p+1][1] = r[3];
                ldsm_x4(r, aBl + p * 16 * ROWB + bk);
                bl[2*p][0] = r[0]; bl[2*p][1] = r[1];
                bl[2*p+1][0] = r[2]; bl[2*p+1][1] = r[3];
            }
#pragma unroll
            for (int mt = 0; mt < 2; ++mt)
#pragma unroll
                for (int nt = 0; nt < 8; ++nt) {
                    mma16816(acc[mt][nt], ah[mt], bh[nt]);
                    mma16816(acc[mt][nt], al[mt], bh[nt]);
                    mma16816(acc[mt][nt], ah[mt], bl[nt]);
                }
        }
        __syncthreads();
    }

    const int mbase = by * 128 + wm * 32;
    const int nloc0 = wn * 64;
#pragma unroll
    for (int mt = 0; mt < 2; ++mt) {
#pragma unroll
        for (int half = 0; half < 2; ++half) {
            const int m = mbase + mt * 16 + (lane >> 2) + half * 8;
#pragma unroll
            for (int nt = 0; nt < 8; ++nt) {
                const int nloc = nloc0 + nt * 8 + 2 * (lane & 3);
                const int n = ncol0 + nloc;
                float v0 = acc[mt][nt][half * 2 + 0] + bias_s[nloc];
                float v1 = acc[mt][nt][half * 2 + 1] + bias_s[nloc + 1];
                if (DO_GELU) {
                    v0 = 0.5f * v0 * (1.0f + erff(v0 * 0.70710678118654752f));
                    v1 = 0.5f * v1 * (1.0f + erff(v1 * 0.70710678118654752f));
                }
                if (HAS_RES) {
                    const float2 rv = *(const float2*)(res + (size_t)m * nout + n);
                    v0 += rv.x; v1 += rv.y;
                }
                if (OUTMODE == 0) {
                    *(float2*)(Cf + (size_t)m * nout + n) = make_float2(v0, v1);
                } else {
                    __nv_bfloat16 h0 = __float2bfloat16(v0);
                    __nv_bfloat16 h1 = __float2bfloat16(v1);
                    __nv_bfloat16 l0 = __float2bfloat16(v0 - __bfloat162float(h0));
                    __nv_bfloat16 l1 = __float2bfloat16(v1 - __bfloat162float(h1));
                    *(__nv_bfloat162*)(chp + (size_t)m * nout + n) = __halves2bfloat162(h0, h1);
                    *(__nv_bfloat162*)(clp + (size_t)m * nout + n) = __halves2bfloat162(l0, l1);
                }
            }
        }
    }
}

// ---------------- Flash attention via mma.sync (bf16x3, causal) -----------------
#define AROWB 144
#define ATT_SMEM (128*AROWB*2 + 64*AROWB*4)

__global__ void __launch_bounds__(256, 2)
attn_mma(const __nv_bfloat16* __restrict__ qhi, const __nv_bfloat16* __restrict__ qlo,
         const __nv_bfloat16* __restrict__ khi, const __nv_bfloat16* __restrict__ klo,
         const __nv_bfloat16* __restrict__ vhi, const __nv_bfloat16* __restrict__ vlo,
         __nv_bfloat16* __restrict__ ohi, __nv_bfloat16* __restrict__ olo) {
    extern __shared__ char sm[];
    const uint32_t sb  = smem_u32(sm);
    const uint32_t sQh = sb;
    const uint32_t sQl = sb + 128 * AROWB;
    const uint32_t sKh = sb + 256 * AROWB;
    const uint32_t sKl = sKh + 64 * AROWB;
    const uint32_t sVh = sKl + 64 * AROWB;
    const uint32_t sVl = sVh + 64 * AROWB;

    const int qt = gridDim.x - 1 - blockIdx.x;
    const int bh = blockIdx.y;
    const int b = bh >> 4, h = bh & 15;
    const size_t base = (size_t)b * SS * DD + (size_t)h * DHH;
    const int q0 = qt * 128;

    const int tid = threadIdx.x, warp = tid >> 5, lane = tid & 31;

#pragma unroll
    for (int u = 0; u < 4; ++u) {
        const int lin = tid + u * 256;
        const int r = lin >> 3, c = lin & 7;
        const size_t go = base + (size_t)(q0 + r) * DD + c * 8;
        cp_async16(sQh + r * AROWB + c * 16, qhi + go);
        cp_async16(sQl + r * AROWB + c * 16, qlo + go);
    }
    cp_commit();

    float sfr[8][4], oac[8][4];
    float m0 = -1e30f, m1 = -1e30f, l0 = 0.f, l1 = 0.f;
#pragma unroll
    for (int j = 0; j < 8; ++j)
#pragma unroll
        for (int e = 0; e < 4; ++e) oac[j][e] = 0.f;

    const uint32_t qbh = sQh + (warp * 16 + (lane & 15)) * AROWB + (((lane >> 4) << 3) << 1);
    const uint32_t qbl = qbh + 128 * AROWB;
    const int krow = (lane & 7) + ((lane >> 4) << 3);
    const uint32_t kof = (((lane >> 3) & 1) << 3) << 1;
    const int vrow = lane & 15;
    const uint32_t vof = (((lane >> 4) << 3)) << 1;

    cp_wait<0>();
    __syncthreads();

    const int ntile = qt * 2 + 2;
    for (int kt = 0; kt < ntile; ++kt) {
        const int k0 = kt * 64;
        __syncthreads();
        {
            const __nv_bfloat16* src0 = khi + base + (size_t)k0 * DD;
            const __nv_bfloat16* src1 = klo + base + (size_t)k0 * DD;
            const __nv_bfloat16* src2 = vhi + base + (size_t)k0 * DD;
            const __nv_bfloat16* src3 = vlo + base + (size_t)k0 * DD;
#pragma unroll
            for (int u = 0; u < 2; ++u) {
                const int lin = tid + u * 256;
                const int rr = lin >> 3, cc = lin & 7;
                const size_t go = (size_t)rr * DD + cc * 8;
                const uint32_t so = rr * AROWB + cc * 16;
                cp_async16(sKh + so, src0 + go);
                cp_async16(sKl + so, src1 + go);
                cp_async16(sVh + so, src2 + go);
                cp_async16(sVl + so, src3 + go);
            }
            cp_commit(); cp_wait<0>();
            __syncthreads();
        }

#pragma unroll
        for (int j = 0; j < 8; ++j)
#pragma unroll
            for (int e = 0; e < 4; ++e) sfr[j][e] = 0.f;
#pragma unroll
        for (int t = 0; t < 4; ++t) {
            uint32_t qah[4], qal[4];
            ldsm_x4(qah, qbh + t * 32);
            ldsm_x4(qal, qbl + t * 32);
#pragma unroll
            for (int g = 0; g < 4; ++g) {
                uint32_t kbh[4], kbl[4];
                const uint32_t ka = (g * 16 + krow) * AROWB + t * 32 + kof;
                ldsm_x4(kbh, sKh + ka);
                ldsm_x4(kbl, sKl + ka);
                mma16816(sfr[2*g],   qah, kbh);
                mma16816(sfr[2*g],   qal, kbh);
                mma16816(sfr[2*g],   qah, kbl);
                mma16816(sfr[2*g+1], qah, kbh + 2);
                mma16816(sfr[2*g+1], qal, kbh + 2);
                mma16816(sfr[2*g+1], qah, kbl + 2);
            }
        }

        const float cs = 0.1803368801111204f;
        const int rg0 = q0 + warp * 16 + (lane >> 2);
        if (kt >= 2 * qt) {
#pragma unroll
            for (int j = 0; j < 8; ++j) {
                const int cb = k0 + j * 8 + 2 * (lane & 3);
#pragma unroll
                for (int e = 0; e < 4; ++e) {
                    const int cg = cb + (e & 1);
                    const int rg = rg0 + ((e >> 1) << 3);
                    const float s = sfr[j][e] * cs;
                    sfr[j][e] = (cg > rg) ? -1e30f : s;
                }
            }
        } else {
#pragma unroll
            for (int j = 0; j < 8; ++j)
#pragma unroll
                for (int e = 0; e < 4; ++e) sfr[j][e] *= cs;
        }
        float mx0 = -1e30f, mx1 = -1e30f;
#pragma unroll
        for (int j = 0; j < 8; ++j) {
            mx0 = fmaxf(mx0, fmaxf(sfr[j][0], sfr[j][1]));
            mx1 = fmaxf(mx1, fmaxf(sfr[j][2], sfr[j][3]));
        }
        mx0 = fmaxf(mx0, __shfl_xor_sync(0xffffffffu, mx0, 1));
        mx0 = fmaxf(mx0, __shfl_xor_sync(0xffffffffu, mx0, 2));
        mx1 = fmaxf(mx1, __shfl_xor_sync(0xffffffffu, mx1, 1));
        mx1 = fmaxf(mx1, __shfl_xor_sync(0xffffffffu, mx1, 2));
        mx0 = fmaxf(mx0, m0);
        mx1 = fmaxf(mx1, m1);
        const float al0 = exp2f(m0 - mx0);
        const float al1 = exp2f(m1 - mx1);
        m0 = mx0; m1 = mx1;
        float s0 = 0.f, s1 = 0.f;
#pragma unroll
        for (int j = 0; j < 8; ++j) {
            float p0 = exp2f(sfr[j][0] - mx0);
            float p1 = exp2f(sfr[j][1] - mx0);
            float p2 = exp2f(sfr[j][2] - mx1);
            float p3 = exp2f(sfr[j][3] - mx1);
            sfr[j][0] = p0; sfr[j][1] = p1; sfr[j][2] = p2; sfr[j][3] = p3;
            s0 += p0 + p1; s1 += p2 + p3;
        }
        s0 += __shfl_xor_sync(0xffffffffu, s0, 1);
        s0 += __shfl_xor_sync(0xffffffffu, s0, 2);
        s1 += __shfl_xor_sync(0xffffffffu, s1, 1);
        s1 += __shfl_xor_sync(0xffffffffu, s1, 2);
        l0 = l0 * al0 + s0;
        l1 = l1 * al1 + s1;
#pragma unroll
        for (int j = 0; j < 8; ++j) {
            oac[j][0] *= al0; oac[j][1] *= al0;
            oac[j][2] *= al1; oac[j][3] *= al1;
        }

#pragma unroll
        for (int t = 0; t < 4; ++t) {
            const float* f0 = sfr[2*t];
            const float* f1 = sfr[2*t+1];
            uint32_t pah[4], pal[4];
            pah[0] = packbf(f0[0], f0[1]);
            pah[1] = packbf(f0[2], f0[3]);
            pah[2] = packbf(f1[0], f1[1]);
            pah[3] = packbf(f1[2], f1[3]);
            pal[0] = packbf(bfres(f0[0]), bfres(f0[1]));
            pal[1] = packbf(bfres(f0[2]), bfres(f0[3]));
            pal[2] = packbf(bfres(f1[0]), bfres(f1[1]));
            pal[3] = packbf(bfres(f1[2]), bfres(f1[3]));
#pragma unroll
            for (int np = 0; np < 4; ++np) {
                uint32_t vbh[4], vbl[4];
                const uint32_t va = (t * 16 + vrow) * AROWB + np * 32 + vof;
                ldsm_x4_t(vbh, sVh + va);
                ldsm_x4_t(vbl, sVl + va);
                mma16816(oac[2*np],   pah, vbh);
                mma16816(oac[2*np],   pal, vbh);
                mma16816(oac[2*np],   pah, vbl);
                mma16816(oac[2*np+1], pah, vbh + 2);
                mma16816(oac[2*np+1], pal, vbh + 2);
                mma16816(oac[2*np+1], pah, vbl + 2);
            }
        }
    }

    const float inv0 = 1.f / l0, inv1 = 1.f / l1;
    const int r0g = q0 + warp * 16 + (lane >> 2);
#pragma unroll
    for (int j = 0; j < 8; ++j) {
        const size_t off0 = base + (size_t)r0g * DD + j * 8 + 2 * (lane & 3);
        const size_t off1 = off0 + (size_t)8 * DD;
        const float v0 = oac[j][0] * inv0, v1 = oac[j][1] * inv0;
        const float v2 = oac[j][2] * inv1, v3 = oac[j][3] * inv1;
        __nv_bfloat16 h0 = __float2bfloat16(v0), h1 = __float2bfloat16(v1);
        __nv_bfloat16 h2 = __float2bfloat16(v2), h3 = __float2bfloat16(v3);
        *(__nv_bfloat162*)(ohi + off0) = __halves2bfloat162(h0, h1);
        *(__nv_bfloat162*)(ohi + off1) = __halves2bfloat162(h2, h3);
        *(__nv_bfloat162*)(olo + off0) = __halves2bfloat162(
            __float2bfloat16(v0 - __bfloat162float(h0)),
            __float2bfloat16(v1 - __bfloat162float(h1)));
        *(__nv_bfloat162*)(olo + off1) = __halves2bfloat162(
            __float2bfloat16(v2 - __bfloat162float(h2)),
            __float2bfloat16(v3 - __bfloat162float(h3)));
    }
}

// ---------------- host launcher -------------------------------------------------
extern "C" void kernel_launch(void* const* d_in, const int* in_sizes, int n_in,
                              void* d_out, int out_size) {
    const float* x     = (const float*)d_in[0];
    const float* ln1_g = (const float*)d_in[1];
    const float* ln1_b = (const float*)d_in[2];
    const float* wq    = (const float*)d_in[3];
    const float* bq    = (const float*)d_in[4];
    const float* wk    = (const float*)d_in[5];
    const float* bk    = (const float*)d_in[6];
    const float* wv    = (const float*)d_in[7];
    const float* bv    = (const float*)d_in[8];
    const float* wo    = (const float*)d_in[9];
    const float* bo    = (const float*)d_in[10];
    const float* ln2_g = (const float*)d_in[11];
    const float* ln2_b = (const float*)d_in[12];
    const float* w1    = (const float*)d_in[13];
    const float* b1    = (const float*)d_in[14];
    const float* w2    = (const float*)d_in[15];
    const float* b2    = (const float*)d_in[16];
    float* out = (float*)d_out;

    __nv_bfloat16 *hhi, *hlo, *qhi, *qlo, *khi, *klo, *vhi, *vlo, *ohi, *olo;
    __nv_bfloat16 *h2hi, *h2lo, *acthi, *actlo;
    __nv_bfloat16 *wqkvh, *wqkvl, *woh, *wol, *w1h, *w1l, *w2h, *w2l;
    float *padd1;
    cudaGetSymbolAddress((void**)&hhi,  g_h_hi);  cudaGetSymbolAddress((void**)&hlo,  g_h_lo);
    cudaGetSymbolAddress((void**)&qhi,  g_q_hi);  cudaGetSymbolAddress((void**)&qlo,  g_q_lo);
    cudaGetSymbolAddress((void**)&khi,  g_k_hi);  cudaGetSymbolAddress((void**)&klo,  g_k_lo);
    cudaGetSymbolAddress((void**)&vhi,  g_v_hi);  cudaGetSymbolAddress((void**)&vlo,  g_v_lo);
    cudaGetSymbolAddress((void**)&ohi,  g_o_hi);  cudaGetSymbolAddress((void**)&olo,  g_o_lo);
    cudaGetSymbolAddress((void**)&padd1,g_add1);
    cudaGetSymbolAddress((void**)&h2hi, g_h2_hi); cudaGetSymbolAddress((void**)&h2lo, g_h2_lo);
    cudaGetSymbolAddress((void**)&acthi,g_act_hi);cudaGetSymbolAddress((void**)&actlo,g_act_lo);
    cudaGetSymbolAddress((void**)&wqkvh,g_wqkv_hi);cudaGetSymbolAddress((void**)&wqkvl,g_wqkv_lo);
    cudaGetSymbolAddress((void**)&woh,  g_wo_hi); cudaGetSymbolAddress((void**)&wol,  g_wo_lo);
    cudaGetSymbolAddress((void**)&w1h,  g_w1_hi); cudaGetSymbolAddress((void**)&w1l,  g_w1_lo);
    cudaGetSymbolAddress((void**)&w2h,  g_w2_hi); cudaGetSymbolAddress((void**)&w2l,  g_w2_lo);

    cudaFuncSetAttribute(tc_gemm<1,false,false,true >, cudaFuncAttributeMaxDynamicSharedMemorySize, GEMM_SMEM);
    cudaFuncSetAttribute(tc_gemm<0,true, false,false>, cudaFuncAttributeMaxDynamicSharedMemorySize, GEMM_SMEM);
    cudaFuncSetAttribute(tc_gemm<1,false,true ,false>, cudaFuncAttributeMaxDynamicSharedMemorySize, GEMM_SMEM);
    cudaFuncSetAttribute(attn_mma, cudaFuncAttributeMaxDynamicSharedMemorySize, ATT_SMEM);

    // launches 1-5: qkv weight splits into concat buffer, wo split, ln1
    wsplit_kernel<<<dim3(DD/32, DD/32), 256>>>(wq, wqkvh,                 wqkvl,                 DD, DD);
    wsplit_kernel<<<dim3(DD/32, DD/32), 256>>>(wk, wqkvh + (size_t)DD*DD, wqkvl + (size_t)DD*DD, DD, DD);
    wsplit_kernel<<<dim3(DD/32, DD/32), 256>>>(wv, wqkvh + (size_t)2*DD*DD, wqkvl + (size_t)2*DD*DD, DD, DD);
    wsplit_kernel<<<dim3(DD/32, DD/32), 256>>>(wo, woh, wol, DD, DD);
    ln_split_kernel<<<NTOK, 256>>>(x, ln1_g, ln1_b, hhi, hlo);

    // launch 6 (ncu-profiled): fused QKV GEMM -> q/k/v bf16 hi/lo
    {
        dim3 grid(3*DD/128, NTOK/128);   // 24 x 32 = 768 CTAs
        tc_gemm<1,false,false,true><<<grid, 256, GEMM_SMEM>>>(
            hhi, hlo, wqkvh, wqkvl, bq, bk, bv, nullptr,
            nullptr, qhi, qlo, khi, klo, vhi, vlo, NTOK, 3*DD, DD);
    }

    // attention (tensor-core flash)
    {
        dim3 grid(SS/128, BB*HH);
        attn_mma<<<grid, 256, ATT_SMEM>>>(qhi, qlo, khi, klo, vhi, vlo, ohi, olo);
    }

    // O-proj + residual: add1 = x + o@wo + bo
    {
        dim3 grid(DD/128, NTOK/128);
        tc_gemm<0,true,false,false><<<grid, 256, GEMM_SMEM>>>(
            ohi, olo, woh, wol, bo, nullptr, nullptr, x,
            padd1, nullptr, nullptr, nullptr, nullptr, nullptr, nullptr, NTOK, DD, DD);
    }

    // MLP weight splits + ln2
    wsplit_kernel<<<dim3(FF/32, DD/32), 256>>>(w1, w1h, w1l, DD, FF);
    wsplit_kernel<<<dim3(DD/32, FF/32), 256>>>(w2, w2h, w2l, FF, DD);
    ln_split_kernel<<<NTOK, 256>>>(padd1, ln2_g, ln2_b, h2hi, h2lo);

    // MLP up + gelu -> bf16 pair
    {
        dim3 grid(FF/128, NTOK/128);
        tc_gemm<1,false,true,false><<<grid, 256, GEMM_SMEM>>>(
            h2hi, h2lo, w1h, w1l, b1, nullptr, nullptr, nullptr,
            nullptr, acthi, actlo, nullptr, nullptr, nullptr, nullptr, NTOK, FF, DD);
    }

    // MLP down + residual -> out
    {
        dim3 grid(DD/128, NTOK/128);
        tc_gemm<0,true,false,false><<<grid, 256, GEMM_SMEM>>>(
            acthi, actlo, w2h, w2l, b2, nullptr, nullptr, padd1,
            out, nullptr, nullptr, nullptr, nullptr, nullptr, nullptr, NTOK, DD, FF);
    }
}